// round 1
// baseline (speedup 1.0000x reference)
#include <cuda_runtime.h>
#include <cstdint>

// ---------------- problem constants ----------------
#define BATCH   32
#define HH      56
#define WW      56
#define CC      192
#define WS      7
#define SS      3
#define NHEAD   6
#define HD      32
#define NWIN    49            // WS*WS
#define NTOK    100352        // BATCH*HH*WW
#define HID     768           // 4*C
#define SCALE   0.17677669529663687f  // 1/sqrt(32)

// ---------------- scratch (device globals; no allocation allowed) ----------------
__device__ float g_xw [ (size_t)NTOK * CC  ];   // LN1+windowed tokens; reused for attn out
__device__ float g_qkv[ (size_t)NTOK * 576 ];   // qkv; reused for LN2 output
__device__ float g_act[ (size_t)NTOK * HID ];   // fc1 activations

// ---------------- LN kernel (warp per token) ----------------
// gather=1: output row m is a windowed token; source is the shifted-roll original token.
__global__ __launch_bounds__(256)
void ln_kernel(const float* __restrict__ in, const float* __restrict__ g,
               const float* __restrict__ b, float* __restrict__ outp, int gather)
{
    int warp = threadIdx.x >> 5, lane = threadIdx.x & 31;
    int m = blockIdx.x * 8 + warp;
    size_t src;
    if (gather) {
        int bb  = m / (HH * WW);
        int r   = m % (HH * WW);
        int win = r / NWIN, pq = r % NWIN;
        int wi = win >> 3, wj = win & 7;
        int p = pq / WS, q = pq % WS;
        int h = wi * WS + p + SS; if (h >= HH) h -= HH;
        int w = wj * WS + q + SS; if (w >= WW) w -= WW;
        src = (size_t)bb * (HH * WW) + h * WW + w;
    } else {
        src = (size_t)m;
    }
    const float* xp = in + src * CC;
    float v[6];
    float sum = 0.f;
#pragma unroll
    for (int u = 0; u < 6; u++) { v[u] = xp[lane + 32 * u]; sum += v[u]; }
#pragma unroll
    for (int o = 16; o; o >>= 1) sum += __shfl_xor_sync(0xffffffffu, sum, o);
    float mu = sum * (1.0f / CC);
    float vs = 0.f;
#pragma unroll
    for (int u = 0; u < 6; u++) { float d = v[u] - mu; vs += d * d; }
#pragma unroll
    for (int o = 16; o; o >>= 1) vs += __shfl_xor_sync(0xffffffffu, vs, o);
    float rstd = rsqrtf(vs * (1.0f / CC) + 1e-5f);
    float* op = outp + (size_t)m * CC;
#pragma unroll
    for (int u = 0; u < 6; u++) {
        int c = lane + 32 * u;
        op[c] = (v[u] - mu) * rstd * g[c] + b[c];
    }
}

// ---------------- generic fp32 GEMM: out[m,n] = sum_k A[m,k]*W[n,k] + bias[n] ----------------
// EPI: 0 none, 1 proj (scatter + residual x), 2 gelu, 3 fc2 (residual in-place on out)
#define BM 64
#define BN 64
#define BKK 16

template<int EPI>
__global__ __launch_bounds__(256)
void gemm_k(const float* __restrict__ A, const float* __restrict__ W,
            const float* __restrict__ bias, float* __restrict__ out,
            int K, int ldo, const float* __restrict__ resid)
{
    __shared__ float As[BKK][BM + 4];
    __shared__ float Bs[BKK][BN + 4];
    const int m0 = blockIdx.x * BM;
    const int n0 = blockIdx.y * BN;
    const int tid = threadIdx.x;
    const int ty = tid >> 4, tx = tid & 15;      // 16x16 thread grid, 4x4 microtile
    const int lrow = tid >> 2;                   // 0..63
    const int lkq  = (tid & 3) << 2;             // 0,4,8,12
    const float* Ag = A + (size_t)(m0 + lrow) * K + lkq;
    const float* Wg = W + (size_t)(n0 + lrow) * K + lkq;

    float acc[4][4] = {};
    for (int k0 = 0; k0 < K; k0 += BKK) {
        float4 av = *(const float4*)(Ag + k0);
        float4 bv = *(const float4*)(Wg + k0);
        As[lkq + 0][lrow] = av.x; As[lkq + 1][lrow] = av.y;
        As[lkq + 2][lrow] = av.z; As[lkq + 3][lrow] = av.w;
        Bs[lkq + 0][lrow] = bv.x; Bs[lkq + 1][lrow] = bv.y;
        Bs[lkq + 2][lrow] = bv.z; Bs[lkq + 3][lrow] = bv.w;
        __syncthreads();
#pragma unroll
        for (int kk = 0; kk < BKK; kk++) {
            float4 a4 = *(const float4*)&As[kk][ty * 4];
            float4 b4 = *(const float4*)&Bs[kk][tx * 4];
            float aa[4] = {a4.x, a4.y, a4.z, a4.w};
            float bb[4] = {b4.x, b4.y, b4.z, b4.w};
#pragma unroll
            for (int i = 0; i < 4; i++)
#pragma unroll
                for (int j = 0; j < 4; j++) acc[i][j] += aa[i] * bb[j];
        }
        __syncthreads();
    }

#pragma unroll
    for (int i = 0; i < 4; i++) {
        int m = m0 + ty * 4 + i;
        size_t orow;
        if (EPI == 1) {
            // windowed token m -> original token (window reverse + roll(+3,+3))
            int bb  = m / (HH * WW);
            int r   = m % (HH * WW);
            int win = r / NWIN, pq = r % NWIN;
            int wi = win >> 3, wj = win & 7;
            int p = pq / WS, q = pq % WS;
            int h = wi * WS + p + SS; if (h >= HH) h -= HH;
            int w = wj * WS + q + SS; if (w >= WW) w -= WW;
            orow = (size_t)bb * (HH * WW) + h * WW + w;
        } else {
            orow = (size_t)m;
        }
#pragma unroll
        for (int j = 0; j < 4; j++) {
            int n = n0 + tx * 4 + j;
            float vv = acc[i][j] + bias[n];
            if (EPI == 2) {
                vv = 0.5f * vv * (1.0f + erff(vv * 0.70710678118654752f));
            }
            if (EPI == 1) {
                out[orow * CC + n] = resid[orow * CC + n] + vv;
            } else if (EPI == 3) {
                out[orow * CC + n] = resid[orow * CC + n] + vv;
            } else {
                out[orow * (size_t)ldo + n] = vv;
            }
        }
    }
}

// ---------------- attention: one block per (window, head) ----------------
__global__ __launch_bounds__(256)
void attn_k(const float* __restrict__ qkv, const float* __restrict__ rpb,
            float* __restrict__ outp)
{
    const int wIdx = blockIdx.x;   // 0..2047
    const int hIdx = blockIdx.y;   // 0..5
    __shared__ float sq[NWIN][HD + 1];
    __shared__ float sk[NWIN][HD + 1];
    __shared__ float sv[NWIN][HD + 1];
    __shared__ float sc[NWIN][NWIN + 1];
    const int tid = threadIdx.x;
    const size_t base = (size_t)wIdx * NWIN;

    for (int idx = tid; idx < NWIN * HD; idx += 256) {
        int i = idx >> 5, d = idx & 31;
        size_t off = (base + i) * 576 + hIdx * HD + d;
        sq[i][d] = qkv[off] * SCALE;
        sk[i][d] = qkv[off + CC];
        sv[i][d] = qkv[off + 2 * CC];
    }
    __syncthreads();

    const int win = wIdx & 63;
    const int wi = win >> 3, wj = win & 7;
    for (int idx = tid; idx < NWIN * NWIN; idx += 256) {
        int i = idx / NWIN, j = idx % NWIN;
        float acc = 0.f;
#pragma unroll
        for (int d = 0; d < HD; d++) acc += sq[i][d] * sk[j][d];
        int pi = i / WS, qi = i % WS, pj = j / WS, qj = j % WS;
        int ridx = (pi - pj + WS - 1) * (2 * WS - 1) + (qi - qj + WS - 1);
        acc += rpb[ridx * NHEAD + hIdx];
        // shift mask: region ids in the shifted image
        int hi = wi * WS + pi, wwi = wj * WS + qi;
        int hj = wi * WS + pj, wwj = wj * WS + qj;
        int ri = (hi < HH - WS ? 0 : (hi < HH - SS ? 1 : 2)) * 3
               + (wwi < WW - WS ? 0 : (wwi < WW - SS ? 1 : 2));
        int rj = (hj < HH - WS ? 0 : (hj < HH - SS ? 1 : 2)) * 3
               + (wwj < WW - WS ? 0 : (wwj < WW - SS ? 1 : 2));
        if (ri != rj) acc -= 100.0f;
        sc[i][j] = acc;
    }
    __syncthreads();

    if (tid < NWIN) {
        float mx = -1e30f;
#pragma unroll 7
        for (int j = 0; j < NWIN; j++) mx = fmaxf(mx, sc[tid][j]);
        float sum = 0.f;
#pragma unroll 7
        for (int j = 0; j < NWIN; j++) { float e = __expf(sc[tid][j] - mx); sc[tid][j] = e; sum += e; }
        float inv = 1.0f / sum;
#pragma unroll 7
        for (int j = 0; j < NWIN; j++) sc[tid][j] *= inv;
    }
    __syncthreads();

    for (int idx = tid; idx < NWIN * HD; idx += 256) {
        int i = idx >> 5, d = idx & 31;
        float acc = 0.f;
#pragma unroll 7
        for (int j = 0; j < NWIN; j++) acc += sc[i][j] * sv[j][d];
        outp[(base + i) * CC + hIdx * HD + d] = acc;
    }
}

// ---------------- launcher ----------------
extern "C" void kernel_launch(void* const* d_in, const int* in_sizes, int n_in,
                              void* d_out, int out_size)
{
    const float* x      = (const float*)d_in[0];
    const float* n1g    = (const float*)d_in[1];
    const float* n1b    = (const float*)d_in[2];
    const float* qkv_w  = (const float*)d_in[3];
    const float* qkv_b  = (const float*)d_in[4];
    const float* proj_w = (const float*)d_in[5];
    const float* proj_b = (const float*)d_in[6];
    const float* rpb    = (const float*)d_in[7];
    const float* n2g    = (const float*)d_in[8];
    const float* n2b    = (const float*)d_in[9];
    const float* fc1w   = (const float*)d_in[10];
    const float* fc1b   = (const float*)d_in[11];
    const float* fc2w   = (const float*)d_in[12];
    const float* fc2b   = (const float*)d_in[13];
    float* out = (float*)d_out;

    float *xw, *qkv, *act;
    cudaGetSymbolAddress((void**)&xw,  g_xw);
    cudaGetSymbolAddress((void**)&qkv, g_qkv);
    cudaGetSymbolAddress((void**)&act, g_act);

    // 1. LN1 + shifted-window gather
    ln_kernel<<<NTOK / 8, 256>>>(x, n1g, n1b, xw, 1);
    // 2. QKV GEMM  (M=100352, N=576, K=192)
    gemm_k<0><<<dim3(NTOK / BM, 576 / BN), 256>>>(xw, qkv_w, qkv_b, qkv, 192, 576, nullptr);
    // 3. windowed attention (writes back into xw)
    attn_k<<<dim3(NTOK / NWIN, NHEAD), 256>>>(qkv, rpb, xw);
    // 4. proj GEMM + window-reverse scatter + residual  -> d_out holds h
    gemm_k<1><<<dim3(NTOK / BM, CC / BN), 256>>>(xw, proj_w, proj_b, out, 192, CC, x);
    // 5. LN2 (reuse qkv buffer)
    ln_kernel<<<NTOK / 8, 256>>>(out, n2g, n2b, qkv, 0);
    // 6. fc1 GEMM + GELU
    gemm_k<2><<<dim3(NTOK / BM, HID / BN), 256>>>(qkv, fc1w, fc1b, act, 192, HID, nullptr);
    // 7. fc2 GEMM + residual (in-place on d_out)
    gemm_k<3><<<dim3(NTOK / BM, CC / BN), 256>>>(act, fc2w, fc2b, out, 768, CC, out);
}

// round 4
// speedup vs baseline: 2.1455x; 2.1455x over previous
#include <cuda_runtime.h>
#include <cstdint>

// ---------------- problem constants ----------------
#define BATCH   32
#define HH      56
#define WW      56
#define CC      192
#define WS      7
#define SS      3
#define NHEAD   6
#define HD      32
#define NWIN    49
#define NTOK    100352
#define HID     768
#define SCALE   0.17677669529663687f

#define GM 128
#define GN 96

// ---------------- scratch ----------------
__device__ float g_xw [ (size_t)NTOK * CC  ];
__device__ float g_qkv[ (size_t)NTOK * 576 ];
__device__ float g_act[ (size_t)NTOK * HID ];

// ---------------- helpers ----------------
__device__ __forceinline__ uint32_t smem_u32(const void* p) {
    uint32_t a;
    asm("{ .reg .u64 t; cvta.to.shared.u64 t, %1; cvt.u32.u64 %0, t; }" : "=r"(a) : "l"(p));
    return a;
}
__device__ __forceinline__ uint32_t f2tf32(float x) {
    uint32_t u;
    asm("cvt.rna.tf32.f32 %0, %1;" : "=r"(u) : "f"(x));
    return u;
}
// windowed token index -> original token index (window reverse + roll +3,+3)
__device__ __forceinline__ size_t win2orig(int m) {
    int bb  = m / (HH * WW);
    int r   = m % (HH * WW);
    int win = r / NWIN, pq = r % NWIN;
    int wi = win >> 3, wj = win & 7;
    int p = pq / WS, q = pq % WS;
    int h = wi * WS + p + SS; if (h >= HH) h -= HH;
    int w = wj * WS + q + SS; if (w >= WW) w -= WW;
    return (size_t)bb * (HH * WW) + h * WW + w;
}

#if defined(__CUDA_ARCH_FEAT_SM103_ALL) || defined(__CUDA_ARCH_FEAT_SM100_ALL)
#define HAVE_TCGEN05 1
#else
#define HAVE_TCGEN05 0
#endif

#if HAVE_TCGEN05
__device__ __forceinline__ uint32_t elect_one() {
    uint32_t p;
    asm volatile("{\n\t.reg .pred p;\n\telect.sync _|p, 0xFFFFFFFF;\n\tselp.b32 %0, 1, 0, p;\n\t}" : "=r"(p));
    return p;
}
#define TC_ALLOC(slot, n)  asm volatile("tcgen05.alloc.cta_group::1.sync.aligned.shared::cta.b32 [%0], %1;" :: "r"(slot), "r"(n) : "memory")
#define TC_DEALLOC(t, n)   asm volatile("tcgen05.dealloc.cta_group::1.sync.aligned.b32 %0, %1;" :: "r"(t), "r"(n))
#define TC_RELINQ()        asm volatile("tcgen05.relinquish_alloc_permit.cta_group::1.sync.aligned;")
#define TC_COMMIT(mb)      asm volatile("tcgen05.commit.cta_group::1.mbarrier::arrive::one.shared::cluster.b64 [%0];" :: "r"(mb) : "memory")
#define TC_WAIT_LD()       asm volatile("tcgen05.wait::ld.sync.aligned;" ::: "memory")
#define TC_FENCE_BEFORE()  asm volatile("tcgen05.fence::before_thread_sync;" ::: "memory")
#define TC_FENCE_AFTER()   asm volatile("tcgen05.fence::after_thread_sync;" ::: "memory")
#define TC_LD_X32(r, addr) \
    asm volatile("tcgen05.ld.sync.aligned.32x32b.x32.b32 " \
        "{%0,%1,%2,%3,%4,%5,%6,%7,%8,%9,%10,%11,%12,%13,%14,%15," \
        "%16,%17,%18,%19,%20,%21,%22,%23,%24,%25,%26,%27,%28,%29,%30,%31}, [%32];" \
        : "=r"((r)[0]),"=r"((r)[1]),"=r"((r)[2]),"=r"((r)[3]),"=r"((r)[4]),"=r"((r)[5]),"=r"((r)[6]),"=r"((r)[7]), \
          "=r"((r)[8]),"=r"((r)[9]),"=r"((r)[10]),"=r"((r)[11]),"=r"((r)[12]),"=r"((r)[13]),"=r"((r)[14]),"=r"((r)[15]), \
          "=r"((r)[16]),"=r"((r)[17]),"=r"((r)[18]),"=r"((r)[19]),"=r"((r)[20]),"=r"((r)[21]),"=r"((r)[22]),"=r"((r)[23]), \
          "=r"((r)[24]),"=r"((r)[25]),"=r"((r)[26]),"=r"((r)[27]),"=r"((r)[28]),"=r"((r)[29]),"=r"((r)[30]),"=r"((r)[31]) \
        : "r"(addr))
static __device__ __forceinline__ uint64_t make_desc(uint32_t saddr) {
    uint64_t d = (uint64_t(2) << 61) | (uint64_t(1) << 46) | (uint64_t(64) << 32) | (uint64_t(1) << 16);
    return d | ((uint64_t)(saddr >> 4) & 0x3FFF);
}
__device__ __forceinline__ void mma_tf32_ss(uint32_t d, uint64_t a, uint64_t b, uint32_t idesc, bool en) {
    uint32_t e = en ? 1u : 0u;
    asm volatile(
        "{\n\t.reg .pred p;\n\tsetp.ne.u32 p, %5, 0;\n\t"
        "tcgen05.mma.cta_group::1.kind::tf32 [%0], %1, %2, %3, {%4, %4, %4, %4}, p;\n\t}"
        :: "r"(d), "l"(a), "l"(b), "r"(idesc), "r"(0u), "r"(e) : "memory");
}
#endif

#define MBAR_INIT(mb, c)   asm volatile("mbarrier.init.shared.b64 [%0], %1;" :: "r"(mb), "r"(c) : "memory")
#define MBAR_WAIT(mb, ph) do { \
    uint32_t _m = (mb), _p = (ph), _d; \
    asm volatile("{\n\t.reg .pred p;\n\tmbarrier.try_wait.parity.acquire.cta.shared::cta.b64 p, [%1], %2;\n\tselp.b32 %0, 1, 0, p;\n\t}" \
        : "=r"(_d) : "r"(_m), "r"(_p) : "memory"); \
    if (!_d) { \
        asm volatile("{\n\t.reg .pred P1;\n\tWL_%=:\n\tmbarrier.try_wait.parity.acquire.cta.shared::cta.b64 P1, [%0], %1, 0x989680;\n\t@P1 bra.uni WD_%=;\n\tbra.uni WL_%=;\n\tWD_%=:\n\t}" \
            :: "r"(_m), "r"(_p) : "memory"); \
    } } while (0)
#define FENCE_ASYNC_SMEM() asm volatile("fence.proxy.async.shared::cta;" ::: "memory")

// idesc: dtype=F32(1)<<4, atype=TF32(2)<<7, btype=TF32(2)<<10, N/8<<17, M/16<<24
#define IDESC ((1u << 4) | (2u << 7) | (2u << 10) | ((GN / 8) << 17) | ((GM / 16) << 24))

// tcgen05 dyn-smem layout (bytes): A 16KB x2, W 12KB x2, ptr, mbar
#define SM_A0   0
#define SM_A1   16384
#define SM_W0   32768
#define SM_W1   45056
#define SM_TPTR 57344
#define SM_MBAR 57352
#define SM_TOTAL 57472

// ---------------- GEMM: out[m,n] = sum_k A[m,k]*W[n,k] + bias[n] ----------------
// EPI: 0 plain, 1 proj(scatter+residual), 2 gelu, 3 residual in-place
template<int EPI>
__global__ __launch_bounds__(256, 2)
void gemm_tc(const float* __restrict__ A, const float* __restrict__ W,
             const float* __restrict__ bias, float* __restrict__ out,
             const float* __restrict__ resid, int K, int ldo)
{
    extern __shared__ char smem[];
    const int tid = threadIdx.x;
    const int warp = tid >> 5, lane = tid & 31;
    const int m0 = blockIdx.x * GM;
    const int n0 = blockIdx.y * GN;

#if HAVE_TCGEN05
    const uint32_t sb = smem_u32(smem);
    const int KC = K >> 5;

    if (warp == 0) { TC_ALLOC(sb + SM_TPTR, 128); TC_RELINQ(); }
    if (tid == 0) MBAR_INIT(sb + SM_MBAR, 1);
    __syncthreads();
    uint32_t tmem;
    asm volatile("ld.shared.b32 %0, [%1];" : "=r"(tmem) : "r"(sb + SM_TPTR));

    const float* Ab = A + (size_t)m0 * K;
    const float* Wb = W + (size_t)n0 * K;

    auto loadA = [&](int kc, int buf) {
        char* base = smem + (buf ? SM_A1 : SM_A0);
        const float* g = Ab + kc * 32;
#pragma unroll
        for (int it = 0; it < 4; it++) {
            int f = tid + it * 256;
            int row = f >> 3, c4 = f & 7;
            const float4 v = *(const float4*)(g + (size_t)row * K + c4 * 4);
            uint32_t off = (row << 7) + (c4 << 4);
            off ^= (off >> 3) & 0x70;
            uint4 u = { f2tf32(v.x), f2tf32(v.y), f2tf32(v.z), f2tf32(v.w) };
            *(uint4*)(base + off) = u;
        }
    };
    auto loadW = [&](int kc, int buf) {
        char* base = smem + (buf ? SM_W1 : SM_W0);
        const float* g = Wb + kc * 32;
#pragma unroll
        for (int it = 0; it < 3; it++) {
            int f = tid + it * 256;
            int row = f >> 3, c4 = f & 7;
            const float4 v = *(const float4*)(g + (size_t)row * K + c4 * 4);
            uint32_t off = (row << 7) + (c4 << 4);
            off ^= (off >> 3) & 0x70;
            uint4 u = { f2tf32(v.x), f2tf32(v.y), f2tf32(v.z), f2tf32(v.w) };
            *(uint4*)(base + off) = u;
        }
    };

    loadA(0, 0); loadW(0, 0);
    FENCE_ASYNC_SMEM();
    __syncthreads();

    for (int kc = 0; kc < KC; kc++) {
        const int buf = kc & 1;
        if (warp == 0 && elect_one()) {
            uint64_t ad = make_desc(sb + (buf ? SM_A1 : SM_A0));
            uint64_t bd = make_desc(sb + (buf ? SM_W1 : SM_W0));
#pragma unroll
            for (int s = 0; s < 4; s++)
                mma_tf32_ss(tmem, ad + s * 2, bd + s * 2, IDESC, (kc > 0) || (s > 0));
            TC_COMMIT(sb + SM_MBAR);
        }
        if (kc + 1 < KC) { loadA(kc + 1, buf ^ 1); loadW(kc + 1, buf ^ 1); }
        FENCE_ASYNC_SMEM();
        MBAR_WAIT(sb + SM_MBAR, kc & 1);
        __syncthreads();
    }

    TC_FENCE_AFTER();

    if (warp < 4) {
        const int m = m0 + warp * 32 + lane;
        size_t orow = (EPI == 1) ? win2orig(m) : (size_t)m;
        float* op = out + orow * (size_t)ldo + n0;
        const float* rp = (EPI == 1 || EPI == 3) ? (resid + orow * CC + n0) : nullptr;
#pragma unroll
        for (int gblk = 0; gblk < 3; gblk++) {
            uint32_t dr[32];
            TC_LD_X32(dr, tmem + gblk * 32);
            TC_WAIT_LD();
            float vv[32];
#pragma unroll
            for (int c = 0; c < 32; c++) {
                float v = __uint_as_float(dr[c]) + bias[n0 + gblk * 32 + c];
                if (EPI == 2) v = 0.5f * v * (1.0f + erff(v * 0.70710678118654752f));
                vv[c] = v;
            }
            if (EPI == 1 || EPI == 3) {
#pragma unroll
                for (int c4 = 0; c4 < 8; c4++) {
                    float4 rv = *(const float4*)(rp + gblk * 32 + c4 * 4);
                    float4 o = { vv[c4*4+0] + rv.x, vv[c4*4+1] + rv.y, vv[c4*4+2] + rv.z, vv[c4*4+3] + rv.w };
                    *(float4*)(op + gblk * 32 + c4 * 4) = o;
                }
            } else {
#pragma unroll
                for (int c4 = 0; c4 < 8; c4++) {
                    float4 o = { vv[c4*4+0], vv[c4*4+1], vv[c4*4+2], vv[c4*4+3] };
                    *(float4*)(op + gblk * 32 + c4 * 4) = o;
                }
            }
        }
        TC_FENCE_BEFORE();
    }
    __syncthreads();
    if (warp == 0) TC_DEALLOC(tmem, 128);

#else  // ---------- fallback: mma.sync m16n8k8 tf32 ----------
    float* As = (float*)smem;                         // [128][33]
    float* Ws = (float*)(smem + 128 * 33 * 4);        // [96][33]
    const int wm = warp >> 1, wn = warp & 1;          // 4x2 warp grid, warp tile 32x48
    const int r = lane >> 2, cq = lane & 3;
    float acc[2][6][4] = {};

    for (int k0 = 0; k0 < K; k0 += 32) {
#pragma unroll
        for (int it = 0; it < 16; it++) {
            int f = tid + it * 256;
            int row = f >> 5, col = f & 31;
            As[row * 33 + col] = __uint_as_float(f2tf32(A[(size_t)(m0 + row) * K + k0 + col]));
        }
#pragma unroll
        for (int it = 0; it < 12; it++) {
            int f = tid + it * 256;
            int row = f >> 5, col = f & 31;
            Ws[row * 33 + col] = __uint_as_float(f2tf32(W[(size_t)(n0 + row) * K + k0 + col]));
        }
        __syncthreads();
#pragma unroll
        for (int kk = 0; kk < 32; kk += 8) {
            uint32_t af[2][4], bf[6][2];
#pragma unroll
            for (int am = 0; am < 2; am++) {
                int mr = wm * 32 + am * 16;
                af[am][0] = __float_as_uint(As[(mr + r)     * 33 + kk + cq]);
                af[am][1] = __float_as_uint(As[(mr + r + 8) * 33 + kk + cq]);
                af[am][2] = __float_as_uint(As[(mr + r)     * 33 + kk + cq + 4]);
                af[am][3] = __float_as_uint(As[(mr + r + 8) * 33 + kk + cq + 4]);
            }
#pragma unroll
            for (int bn = 0; bn < 6; bn++) {
                int nc = wn * 48 + bn * 8 + r;
                bf[bn][0] = __float_as_uint(Ws[nc * 33 + kk + cq]);
                bf[bn][1] = __float_as_uint(Ws[nc * 33 + kk + cq + 4]);
            }
#pragma unroll
            for (int am = 0; am < 2; am++)
#pragma unroll
                for (int bn = 0; bn < 6; bn++)
                    asm volatile("mma.sync.aligned.m16n8k8.row.col.f32.tf32.tf32.f32 "
                        "{%0,%1,%2,%3}, {%4,%5,%6,%7}, {%8,%9}, {%0,%1,%2,%3};"
                        : "+f"(acc[am][bn][0]), "+f"(acc[am][bn][1]),
                          "+f"(acc[am][bn][2]), "+f"(acc[am][bn][3])
                        : "r"(af[am][0]), "r"(af[am][1]), "r"(af[am][2]), "r"(af[am][3]),
                          "r"(bf[bn][0]), "r"(bf[bn][1]));
        }
        __syncthreads();
    }

#pragma unroll
    for (int am = 0; am < 2; am++)
#pragma unroll
    for (int rr = 0; rr < 2; rr++) {
        int m = m0 + wm * 32 + am * 16 + r + rr * 8;
        size_t orow = (EPI == 1) ? win2orig(m) : (size_t)m;
#pragma unroll
        for (int bn = 0; bn < 6; bn++)
#pragma unroll
        for (int c2 = 0; c2 < 2; c2++) {
            int n = n0 + wn * 48 + bn * 8 + cq * 2 + c2;
            float v = acc[am][bn][rr * 2 + c2] + bias[n];
            if (EPI == 2) v = 0.5f * v * (1.0f + erff(v * 0.70710678118654752f));
            if (EPI == 1 || EPI == 3) v += resid[orow * CC + n];
            out[orow * (size_t)ldo + n] = v;
        }
    }
#endif
}

// ---------------- LN kernel (warp per token) ----------------
__global__ __launch_bounds__(256)
void ln_kernel(const float* __restrict__ in, const float* __restrict__ g,
               const float* __restrict__ b, float* __restrict__ outp, int gather)
{
    int warp = threadIdx.x >> 5, lane = threadIdx.x & 31;
    int m = blockIdx.x * 8 + warp;
    size_t src = gather ? win2orig(m) : (size_t)m;
    const float* xp = in + src * CC;
    float v[6];
    float sum = 0.f;
#pragma unroll
    for (int u = 0; u < 6; u++) { v[u] = xp[lane + 32 * u]; sum += v[u]; }
#pragma unroll
    for (int o = 16; o; o >>= 1) sum += __shfl_xor_sync(0xffffffffu, sum, o);
    float mu = sum * (1.0f / CC);
    float vs = 0.f;
#pragma unroll
    for (int u = 0; u < 6; u++) { float d = v[u] - mu; vs += d * d; }
#pragma unroll
    for (int o = 16; o; o >>= 1) vs += __shfl_xor_sync(0xffffffffu, vs, o);
    float rstd = rsqrtf(vs * (1.0f / CC) + 1e-5f);
    float* op = outp + (size_t)m * CC;
#pragma unroll
    for (int u = 0; u < 6; u++) {
        int c = lane + 32 * u;
        op[c] = (v[u] - mu) * rstd * g[c] + b[c];
    }
}

// ---------------- attention ----------------
__global__ __launch_bounds__(256)
void attn_k(const float* __restrict__ qkv, const float* __restrict__ rpb,
            float* __restrict__ outp)
{
    const int wIdx = blockIdx.x;
    const int hIdx = blockIdx.y;
    __shared__ float sq[NWIN][HD + 1];
    __shared__ float sk[NWIN][HD + 1];
    __shared__ float sv[NWIN][HD + 1];
    __shared__ float sc[NWIN][NWIN + 1];
    const int tid = threadIdx.x;
    const size_t base = (size_t)wIdx * NWIN;

    for (int idx = tid; idx < NWIN * HD; idx += 256) {
        int i = idx >> 5, d = idx & 31;
        size_t off = (base + i) * 576 + hIdx * HD + d;
        sq[i][d] = qkv[off] * SCALE;
        sk[i][d] = qkv[off + CC];
        sv[i][d] = qkv[off + 2 * CC];
    }
    __syncthreads();

    const int win = wIdx & 63;
    const int wi = win >> 3, wj = win & 7;
    for (int idx = tid; idx < NWIN * NWIN; idx += 256) {
        int i = idx / NWIN, j = idx % NWIN;
        float acc = 0.f;
#pragma unroll
        for (int d = 0; d < HD; d++) acc += sq[i][d] * sk[j][d];
        int pi = i / WS, qi = i % WS, pj = j / WS, qj = j % WS;
        int ridx = (pi - pj + WS - 1) * (2 * WS - 1) + (qi - qj + WS - 1);
        acc += rpb[ridx * NHEAD + hIdx];
        int hi = wi * WS + pi, wwi = wj * WS + qi;
        int hj = wi * WS + pj, wwj = wj * WS + qj;
        int ri = (hi < HH - WS ? 0 : (hi < HH - SS ? 1 : 2)) * 3
               + (wwi < WW - WS ? 0 : (wwi < WW - SS ? 1 : 2));
        int rj = (hj < HH - WS ? 0 : (hj < HH - SS ? 1 : 2)) * 3
               + (wwj < WW - WS ? 0 : (wwj < WW - SS ? 1 : 2));
        if (ri != rj) acc -= 100.0f;
        sc[i][j] = acc;
    }
    __syncthreads();

    if (tid < NWIN) {
        float mx = -1e30f;
#pragma unroll 7
        for (int j = 0; j < NWIN; j++) mx = fmaxf(mx, sc[tid][j]);
        float sum = 0.f;
#pragma unroll 7
        for (int j = 0; j < NWIN; j++) { float e = __expf(sc[tid][j] - mx); sc[tid][j] = e; sum += e; }
        float inv = 1.0f / sum;
#pragma unroll 7
        for (int j = 0; j < NWIN; j++) sc[tid][j] *= inv;
    }
    __syncthreads();

    for (int idx = tid; idx < NWIN * HD; idx += 256) {
        int i = idx >> 5, d = idx & 31;
        float acc = 0.f;
#pragma unroll 7
        for (int j = 0; j < NWIN; j++) acc += sc[i][j] * sv[j][d];
        outp[(base + i) * CC + hIdx * HD + d] = acc;
    }
}

// ---------------- launcher ----------------
extern "C" void kernel_launch(void* const* d_in, const int* in_sizes, int n_in,
                              void* d_out, int out_size)
{
    const float* x      = (const float*)d_in[0];
    const float* n1g    = (const float*)d_in[1];
    const float* n1b    = (const float*)d_in[2];
    const float* qkv_w  = (const float*)d_in[3];
    const float* qkv_b  = (const float*)d_in[4];
    const float* proj_w = (const float*)d_in[5];
    const float* proj_b = (const float*)d_in[6];
    const float* rpb    = (const float*)d_in[7];
    const float* n2g    = (const float*)d_in[8];
    const float* n2b    = (const float*)d_in[9];
    const float* fc1w   = (const float*)d_in[10];
    const float* fc1b   = (const float*)d_in[11];
    const float* fc2w   = (const float*)d_in[12];
    const float* fc2b   = (const float*)d_in[13];
    float* out = (float*)d_out;

    float *xw, *qkv, *act;
    cudaGetSymbolAddress((void**)&xw,  g_xw);
    cudaGetSymbolAddress((void**)&qkv, g_qkv);
    cudaGetSymbolAddress((void**)&act, g_act);

    cudaFuncSetAttribute(gemm_tc<0>, cudaFuncAttributeMaxDynamicSharedMemorySize, SM_TOTAL);
    cudaFuncSetAttribute(gemm_tc<1>, cudaFuncAttributeMaxDynamicSharedMemorySize, SM_TOTAL);
    cudaFuncSetAttribute(gemm_tc<2>, cudaFuncAttributeMaxDynamicSharedMemorySize, SM_TOTAL);
    cudaFuncSetAttribute(gemm_tc<3>, cudaFuncAttributeMaxDynamicSharedMemorySize, SM_TOTAL);

    // 1. LN1 + shifted-window gather
    ln_kernel<<<NTOK / 8, 256>>>(x, n1g, n1b, xw, 1);
    // 2. QKV: M=100352, N=576, K=192
    gemm_tc<0><<<dim3(NTOK / GM, 576 / GN), 256, SM_TOTAL>>>(xw, qkv_w, qkv_b, qkv, nullptr, 192, 576);
    // 3. windowed attention (writes into xw)
    attn_k<<<dim3(NTOK / NWIN, NHEAD), 256>>>(qkv, rpb, xw);
    // 4. proj + scatter + residual -> d_out
    gemm_tc<1><<<dim3(NTOK / GM, CC / GN), 256, SM_TOTAL>>>(xw, proj_w, proj_b, out, x, 192, CC);
    // 5. LN2 (reuse qkv buffer)
    ln_kernel<<<NTOK / 8, 256>>>(out, n2g, n2b, qkv, 0);
    // 6. fc1 + GELU: N=768
    gemm_tc<2><<<dim3(NTOK / GM, HID / GN), 256, SM_TOTAL>>>(qkv, fc1w, fc1b, act, nullptr, 192, HID);
    // 7. fc2 + residual (in-place on d_out): K=768
    gemm_tc<3><<<dim3(NTOK / GM, CC / GN), 256, SM_TOTAL>>>(act, fc2w, fc2b, out, out, 768, CC);
}

// round 6
// speedup vs baseline: 2.4548x; 1.1442x over previous
#include <cuda_runtime.h>
#include <cstdint>

// ---------------- problem constants ----------------
#define BATCH   32
#define HH      56
#define WW      56
#define CC      192
#define WS      7
#define SS      3
#define NHEAD   6
#define HD      32
#define NWIN    49
#define NTOK    100352
#define HID     768
#define SCALE   0.17677669529663687f

#define GM 128
#define GN 192

// ---------------- scratch ----------------
__device__ float g_xw [ (size_t)NTOK * CC  ];
__device__ float g_qkv[ (size_t)NTOK * 576 ];
__device__ float g_act[ (size_t)NTOK * HID ];

// ---------------- helpers ----------------
__device__ __forceinline__ uint32_t smem_u32(const void* p) {
    uint32_t a;
    asm("{ .reg .u64 t; cvta.to.shared.u64 t, %1; cvt.u32.u64 %0, t; }" : "=r"(a) : "l"(p));
    return a;
}
__device__ __forceinline__ uint32_t f2tf32(float x) {
    uint32_t u;
    asm("cvt.rna.tf32.f32 %0, %1;" : "=r"(u) : "f"(x));
    return u;
}
// windowed token index -> original token index (window reverse + roll +3,+3)
__device__ __forceinline__ size_t win2orig(int m) {
    int bb  = m / (HH * WW);
    int r   = m % (HH * WW);
    int win = r / NWIN, pq = r % NWIN;
    int wi = win >> 3, wj = win & 7;
    int p = pq / WS, q = pq % WS;
    int h = wi * WS + p + SS; if (h >= HH) h -= HH;
    int w = wj * WS + q + SS; if (w >= WW) w -= WW;
    return (size_t)bb * (HH * WW) + h * WW + w;
}

#if defined(__CUDA_ARCH_FEAT_SM103_ALL) || defined(__CUDA_ARCH_FEAT_SM100_ALL)
#define HAVE_TCGEN05 1
#else
#define HAVE_TCGEN05 0
#endif

#if HAVE_TCGEN05
__device__ __forceinline__ uint32_t elect_one() {
    uint32_t p;
    asm volatile("{\n\t.reg .pred p;\n\telect.sync _|p, 0xFFFFFFFF;\n\tselp.b32 %0, 1, 0, p;\n\t}" : "=r"(p));
    return p;
}
#define TC_ALLOC(slot, n)  asm volatile("tcgen05.alloc.cta_group::1.sync.aligned.shared::cta.b32 [%0], %1;" :: "r"(slot), "r"(n) : "memory")
#define TC_DEALLOC(t, n)   asm volatile("tcgen05.dealloc.cta_group::1.sync.aligned.b32 %0, %1;" :: "r"(t), "r"(n))
#define TC_RELINQ()        asm volatile("tcgen05.relinquish_alloc_permit.cta_group::1.sync.aligned;")
#define TC_COMMIT(mb)      asm volatile("tcgen05.commit.cta_group::1.mbarrier::arrive::one.shared::cluster.b64 [%0];" :: "r"(mb) : "memory")
#define TC_WAIT_LD()       asm volatile("tcgen05.wait::ld.sync.aligned;" ::: "memory")
#define TC_FENCE_BEFORE()  asm volatile("tcgen05.fence::before_thread_sync;" ::: "memory")
#define TC_FENCE_AFTER()   asm volatile("tcgen05.fence::after_thread_sync;" ::: "memory")
#define TC_LD_X32(r, addr) \
    asm volatile("tcgen05.ld.sync.aligned.32x32b.x32.b32 " \
        "{%0,%1,%2,%3,%4,%5,%6,%7,%8,%9,%10,%11,%12,%13,%14,%15," \
        "%16,%17,%18,%19,%20,%21,%22,%23,%24,%25,%26,%27,%28,%29,%30,%31}, [%32];" \
        : "=r"((r)[0]),"=r"((r)[1]),"=r"((r)[2]),"=r"((r)[3]),"=r"((r)[4]),"=r"((r)[5]),"=r"((r)[6]),"=r"((r)[7]), \
          "=r"((r)[8]),"=r"((r)[9]),"=r"((r)[10]),"=r"((r)[11]),"=r"((r)[12]),"=r"((r)[13]),"=r"((r)[14]),"=r"((r)[15]), \
          "=r"((r)[16]),"=r"((r)[17]),"=r"((r)[18]),"=r"((r)[19]),"=r"((r)[20]),"=r"((r)[21]),"=r"((r)[22]),"=r"((r)[23]), \
          "=r"((r)[24]),"=r"((r)[25]),"=r"((r)[26]),"=r"((r)[27]),"=r"((r)[28]),"=r"((r)[29]),"=r"((r)[30]),"=r"((r)[31]) \
        : "r"(addr))
static __device__ __forceinline__ uint64_t make_desc(uint32_t saddr) {
    uint64_t d = (uint64_t(2) << 61) | (uint64_t(1) << 46) | (uint64_t(64) << 32) | (uint64_t(1) << 16);
    return d | ((uint64_t)(saddr >> 4) & 0x3FFF);
}
__device__ __forceinline__ void mma_tf32_ss(uint32_t d, uint64_t a, uint64_t b, uint32_t idesc, bool en) {
    uint32_t e = en ? 1u : 0u;
    asm volatile(
        "{\n\t.reg .pred p;\n\tsetp.ne.u32 p, %5, 0;\n\t"
        "tcgen05.mma.cta_group::1.kind::tf32 [%0], %1, %2, %3, {%4, %4, %4, %4}, p;\n\t}"
        :: "r"(d), "l"(a), "l"(b), "r"(idesc), "r"(0u), "r"(e) : "memory");
}
#endif

#define MBAR_INIT(mb, c)   asm volatile("mbarrier.init.shared.b64 [%0], %1;" :: "r"(mb), "r"(c) : "memory")
#define MBAR_WAIT(mb, ph) do { \
    uint32_t _m = (mb), _p = (ph), _d; \
    asm volatile("{\n\t.reg .pred p;\n\tmbarrier.try_wait.parity.acquire.cta.shared::cta.b64 p, [%1], %2;\n\tselp.b32 %0, 1, 0, p;\n\t}" \
        : "=r"(_d) : "r"(_m), "r"(_p) : "memory"); \
    if (!_d) { \
        asm volatile("{\n\t.reg .pred P1;\n\tWL_%=:\n\tmbarrier.try_wait.parity.acquire.cta.shared::cta.b64 P1, [%0], %1, 0x989680;\n\t@P1 bra.uni WD_%=;\n\tbra.uni WL_%=;\n\tWD_%=:\n\t}" \
            :: "r"(_m), "r"(_p) : "memory"); \
    } } while (0)
#define FENCE_ASYNC_SMEM() asm volatile("fence.proxy.async.shared::cta;" ::: "memory")

// idesc: dtype=F32(1)<<4, atype=TF32(2)<<7, btype=TF32(2)<<10, N/8<<17, M/16<<24
#define IDESC ((1u << 4) | (2u << 7) | (2u << 10) | ((GN / 8) << 17) | ((GM / 16) << 24))

// dyn-smem layout (bytes): A 16KB x2, W 24KB x2, ptr, 2 mbars
#define SM_A0   0
#define SM_A1   16384
#define SM_W0   32768
#define SM_W1   57344
#define SM_TPTR 81920
#define SM_MBAR 81928
#define SM_TOTAL 81960

// ---------------- GEMM: out[m,n] = sum_k A[m,k]*W[n,k] + bias[n] ----------------
// EPI: 0 plain, 1 proj(scatter+residual), 2 gelu, 3 residual in-place
template<int EPI>
__global__ __launch_bounds__(256, 2)
void gemm_tc(const float* __restrict__ A, const float* __restrict__ W,
             const float* __restrict__ bias, float* __restrict__ out,
             const float* __restrict__ resid, int K, int ldo)
{
    extern __shared__ char smem[];
    const int tid = threadIdx.x;
    const int warp = tid >> 5, lane = tid & 31;
    const int m0 = blockIdx.x * GM;
    const int n0 = blockIdx.y * GN;

#if HAVE_TCGEN05
    const uint32_t sb = smem_u32(smem);
    const int KC = K >> 5;

    if (warp == 0) { TC_ALLOC(sb + SM_TPTR, 256); TC_RELINQ(); }
    if (tid == 0) { MBAR_INIT(sb + SM_MBAR, 1); MBAR_INIT(sb + SM_MBAR + 8, 1); }
    __syncthreads();
    uint32_t tmem;
    asm volatile("ld.shared.b32 %0, [%1];" : "=r"(tmem) : "r"(sb + SM_TPTR));

    const float* Ab = A + (size_t)m0 * K;
    const float* Wb = W + (size_t)n0 * K;

    auto loadA = [&](int kc, int buf) {
        char* base = smem + (buf ? SM_A1 : SM_A0);
        const float* g = Ab + kc * 32;
#pragma unroll
        for (int it = 0; it < 4; it++) {
            int f = tid + it * 256;                 // 1024 float4
            int row = f >> 3, c4 = f & 7;
            const float4 v = *(const float4*)(g + (size_t)row * K + c4 * 4);
            uint32_t off = (row << 7) + (c4 << 4);
            off ^= (off >> 3) & 0x70;
            uint4 u = { f2tf32(v.x), f2tf32(v.y), f2tf32(v.z), f2tf32(v.w) };
            *(uint4*)(base + off) = u;
        }
    };
    auto loadW = [&](int kc, int buf) {
        char* base = smem + (buf ? SM_W1 : SM_W0);
        const float* g = Wb + kc * 32;
#pragma unroll
        for (int it = 0; it < 6; it++) {
            int f = tid + it * 256;                 // 1536 float4
            int row = f >> 3, c4 = f & 7;
            const float4 v = *(const float4*)(g + (size_t)row * K + c4 * 4);
            uint32_t off = (row << 7) + (c4 << 4);
            off ^= (off >> 3) & 0x70;
            uint4 u = { f2tf32(v.x), f2tf32(v.y), f2tf32(v.z), f2tf32(v.w) };
            *(uint4*)(base + off) = u;
        }
    };

    loadA(0, 0); loadW(0, 0);
    FENCE_ASYNC_SMEM();
    __syncthreads();

    // double-buffered ring: commit chunk kc -> mbar[kc&1]; before overwriting a
    // buffer, wait its own mbar at its per-buffer phase. Waits per mbar are in
    // strict phase order; <=1 outstanding arrival per mbar => no parity wrap.
    for (int kc = 0; kc < KC; kc++) {
        const int buf = kc & 1;
        if (warp == 0 && elect_one()) {
            uint64_t ad = make_desc(sb + (buf ? SM_A1 : SM_A0));
            uint64_t bd = make_desc(sb + (buf ? SM_W1 : SM_W0));
#pragma unroll
            for (int s = 0; s < 4; s++)
                mma_tf32_ss(tmem, ad + s * 2, bd + s * 2, IDESC, (kc > 0) || (s > 0));
            TC_COMMIT(sb + SM_MBAR + 8 * buf);
        }
        if (kc + 1 < KC) {
            if (kc >= 1) {
                int pk = kc - 1;   // chunk last using buffer buf^1
                MBAR_WAIT(sb + SM_MBAR + 8 * (pk & 1), (pk >> 1) & 1);
            }
            loadA(kc + 1, buf ^ 1); loadW(kc + 1, buf ^ 1);
            FENCE_ASYNC_SMEM();
        }
        __syncthreads();
    }
    {
        int pk = KC - 1;
        MBAR_WAIT(sb + SM_MBAR + 8 * (pk & 1), (pk >> 1) & 1);
    }

    TC_FENCE_AFTER();

    if (warp < 4) {
        const int m = m0 + warp * 32 + lane;
        size_t orow = (EPI == 1) ? win2orig(m) : (size_t)m;
        float* op = out + orow * (size_t)ldo + n0;
        const float* rp = (EPI == 1 || EPI == 3) ? (resid + orow * CC + n0) : nullptr;
#pragma unroll
        for (int gblk = 0; gblk < GN / 32; gblk++) {
            uint32_t dr[32];
            TC_LD_X32(dr, tmem + gblk * 32);
            TC_WAIT_LD();
            float vv[32];
#pragma unroll
            for (int c = 0; c < 32; c++) {
                float v = __uint_as_float(dr[c]) + bias[n0 + gblk * 32 + c];
                if (EPI == 2) v = 0.5f * v * (1.0f + erff(v * 0.70710678118654752f));
                vv[c] = v;
            }
            if (EPI == 1 || EPI == 3) {
#pragma unroll
                for (int c4 = 0; c4 < 8; c4++) {
                    float4 rv = *(const float4*)(rp + gblk * 32 + c4 * 4);
                    float4 o = { vv[c4*4+0] + rv.x, vv[c4*4+1] + rv.y, vv[c4*4+2] + rv.z, vv[c4*4+3] + rv.w };
                    *(float4*)(op + gblk * 32 + c4 * 4) = o;
                }
            } else {
#pragma unroll
                for (int c4 = 0; c4 < 8; c4++) {
                    float4 o = { vv[c4*4+0], vv[c4*4+1], vv[c4*4+2], vv[c4*4+3] };
                    *(float4*)(op + gblk * 32 + c4 * 4) = o;
                }
            }
        }
        TC_FENCE_BEFORE();
    }
    __syncthreads();
    if (warp == 0) TC_DEALLOC(tmem, 256);

#else  // ---------- fallback: mma.sync m16n8k8 tf32 ----------
    float* As = (float*)smem;                         // [128][33]
    float* Ws = (float*)(smem + 128 * 33 * 4);        // [GN][33]
    const int wm = warp >> 1, wn = warp & 1;          // 4x2 warp grid, warp tile 32x(GN/2)
    const int r = lane >> 2, cq = lane & 3;
    const int NB = GN / 16;                           // bn blocks of 8 cols per half
    float acc[2][NB][4] = {};

    for (int k0 = 0; k0 < K; k0 += 32) {
#pragma unroll
        for (int it = 0; it < 16; it++) {
            int f = tid + it * 256;
            int row = f >> 5, col = f & 31;
            As[row * 33 + col] = __uint_as_float(f2tf32(A[(size_t)(m0 + row) * K + k0 + col]));
        }
#pragma unroll
        for (int it = 0; it < GN / 8; it++) {
            int f = tid + it * 256;
            int row = f >> 5, col = f & 31;
            Ws[row * 33 + col] = __uint_as_float(f2tf32(W[(size_t)(n0 + row) * K + k0 + col]));
        }
        __syncthreads();
#pragma unroll
        for (int kk = 0; kk < 32; kk += 8) {
            uint32_t af[2][4], bf[NB][2];
#pragma unroll
            for (int am = 0; am < 2; am++) {
                int mr = wm * 32 + am * 16;
                af[am][0] = __float_as_uint(As[(mr + r)     * 33 + kk + cq]);
                af[am][1] = __float_as_uint(As[(mr + r + 8) * 33 + kk + cq]);
                af[am][2] = __float_as_uint(As[(mr + r)     * 33 + kk + cq + 4]);
                af[am][3] = __float_as_uint(As[(mr + r + 8) * 33 + kk + cq + 4]);
            }
#pragma unroll
            for (int bn = 0; bn < NB; bn++) {
                int nc = wn * (GN / 2) + bn * 8 + r;
                bf[bn][0] = __float_as_uint(Ws[nc * 33 + kk + cq]);
                bf[bn][1] = __float_as_uint(Ws[nc * 33 + kk + cq + 4]);
            }
#pragma unroll
            for (int am = 0; am < 2; am++)
#pragma unroll
                for (int bn = 0; bn < NB; bn++)
                    asm volatile("mma.sync.aligned.m16n8k8.row.col.f32.tf32.tf32.f32 "
                        "{%0,%1,%2,%3}, {%4,%5,%6,%7}, {%8,%9}, {%0,%1,%2,%3};"
                        : "+f"(acc[am][bn][0]), "+f"(acc[am][bn][1]),
                          "+f"(acc[am][bn][2]), "+f"(acc[am][bn][3])
                        : "r"(af[am][0]), "r"(af[am][1]), "r"(af[am][2]), "r"(af[am][3]),
                          "r"(bf[bn][0]), "r"(bf[bn][1]));
        }
        __syncthreads();
    }

#pragma unroll
    for (int am = 0; am < 2; am++)
#pragma unroll
    for (int rr = 0; rr < 2; rr++) {
        int m = m0 + wm * 32 + am * 16 + r + rr * 8;
        size_t orow = (EPI == 1) ? win2orig(m) : (size_t)m;
#pragma unroll
        for (int bn = 0; bn < NB; bn++)
#pragma unroll
        for (int c2 = 0; c2 < 2; c2++) {
            int n = n0 + wn * (GN / 2) + bn * 8 + cq * 2 + c2;
            float v = acc[am][bn][rr * 2 + c2] + bias[n];
            if (EPI == 2) v = 0.5f * v * (1.0f + erff(v * 0.70710678118654752f));
            if (EPI == 1 || EPI == 3) v += resid[orow * CC + n];
            out[orow * (size_t)ldo + n] = v;
        }
    }
#endif
}

// ---------------- LN kernel (warp per token) ----------------
__global__ __launch_bounds__(256)
void ln_kernel(const float* __restrict__ in, const float* __restrict__ g,
               const float* __restrict__ b, float* __restrict__ outp, int gather)
{
    int warp = threadIdx.x >> 5, lane = threadIdx.x & 31;
    int m = blockIdx.x * 8 + warp;
    size_t src = gather ? win2orig(m) : (size_t)m;
    const float* xp = in + src * CC;
    float v[6];
    float sum = 0.f;
#pragma unroll
    for (int u = 0; u < 6; u++) { v[u] = xp[lane + 32 * u]; sum += v[u]; }
#pragma unroll
    for (int o = 16; o; o >>= 1) sum += __shfl_xor_sync(0xffffffffu, sum, o);
    float mu = sum * (1.0f / CC);
    float vs = 0.f;
#pragma unroll
    for (int u = 0; u < 6; u++) { float d = v[u] - mu; vs += d * d; }
#pragma unroll
    for (int o = 16; o; o >>= 1) vs += __shfl_xor_sync(0xffffffffu, vs, o);
    float rstd = rsqrtf(vs * (1.0f / CC) + 1e-5f);
    float* op = outp + (size_t)m * CC;
#pragma unroll
    for (int u = 0; u < 6; u++) {
        int c = lane + 32 * u;
        op[c] = (v[u] - mu) * rstd * g[c] + b[c];
    }
}

// ---------------- attention ----------------
__global__ __launch_bounds__(256)
void attn_k(const float* __restrict__ qkv, const float* __restrict__ rpb,
            float* __restrict__ outp)
{
    const int wIdx = blockIdx.x;
    const int hIdx = blockIdx.y;
    __shared__ float sq[NWIN][HD + 1];
    __shared__ float sk[NWIN][HD + 1];
    __shared__ float sv[NWIN][HD + 1];
    __shared__ float sc[NWIN][NWIN + 1];
    const int tid = threadIdx.x;
    const size_t base = (size_t)wIdx * NWIN;

    for (int idx = tid; idx < NWIN * HD; idx += 256) {
        int i = idx >> 5, d = idx & 31;
        size_t off = (base + i) * 576 + hIdx * HD + d;
        sq[i][d] = qkv[off] * SCALE;
        sk[i][d] = qkv[off + CC];
        sv[i][d] = qkv[off + 2 * CC];
    }
    __syncthreads();

    const int win = wIdx & 63;
    const int wi = win >> 3, wj = win & 7;
    for (int idx = tid; idx < NWIN * NWIN; idx += 256) {
        int i = idx / NWIN, j = idx % NWIN;
        float acc = 0.f;
#pragma unroll
        for (int d = 0; d < HD; d++) acc += sq[i][d] * sk[j][d];
        int pi = i / WS, qi = i % WS, pj = j / WS, qj = j % WS;
        int ridx = (pi - pj + WS - 1) * (2 * WS - 1) + (qi - qj + WS - 1);
        acc += rpb[ridx * NHEAD + hIdx];
        int hi = wi * WS + pi, wwi = wj * WS + qi;
        int hj = wi * WS + pj, wwj = wj * WS + qj;
        int ri = (hi < HH - WS ? 0 : (hi < HH - SS ? 1 : 2)) * 3
               + (wwi < WW - WS ? 0 : (wwi < WW - SS ? 1 : 2));
        int rj = (hj < HH - WS ? 0 : (hj < HH - SS ? 1 : 2)) * 3
               + (wwj < WW - WS ? 0 : (wwj < WW - SS ? 1 : 2));
        if (ri != rj) acc -= 100.0f;
        sc[i][j] = acc;
    }
    __syncthreads();

    if (tid < NWIN) {
        float mx = -1e30f;
#pragma unroll 7
        for (int j = 0; j < NWIN; j++) mx = fmaxf(mx, sc[tid][j]);
        float sum = 0.f;
#pragma unroll 7
        for (int j = 0; j < NWIN; j++) { float e = __expf(sc[tid][j] - mx); sc[tid][j] = e; sum += e; }
        float inv = 1.0f / sum;
#pragma unroll 7
        for (int j = 0; j < NWIN; j++) sc[tid][j] *= inv;
    }
    __syncthreads();

    for (int idx = tid; idx < NWIN * HD; idx += 256) {
        int i = idx >> 5, d = idx & 31;
        float acc = 0.f;
#pragma unroll 7
        for (int j = 0; j < NWIN; j++) acc += sc[i][j] * sv[j][d];
        outp[(base + i) * CC + hIdx * HD + d] = acc;
    }
}

// ---------------- launcher ----------------
extern "C" void kernel_launch(void* const* d_in, const int* in_sizes, int n_in,
                              void* d_out, int out_size)
{
    const float* x      = (const float*)d_in[0];
    const float* n1g    = (const float*)d_in[1];
    const float* n1b    = (const float*)d_in[2];
    const float* qkv_w  = (const float*)d_in[3];
    const float* qkv_b  = (const float*)d_in[4];
    const float* proj_w = (const float*)d_in[5];
    const float* proj_b = (const float*)d_in[6];
    const float* rpb    = (const float*)d_in[7];
    const float* n2g    = (const float*)d_in[8];
    const float* n2b    = (const float*)d_in[9];
    const float* fc1w   = (const float*)d_in[10];
    const float* fc1b   = (const float*)d_in[11];
    const float* fc2w   = (const float*)d_in[12];
    const float* fc2b   = (const float*)d_in[13];
    float* out = (float*)d_out;

    float *xw, *qkv, *act;
    cudaGetSymbolAddress((void**)&xw,  g_xw);
    cudaGetSymbolAddress((void**)&qkv, g_qkv);
    cudaGetSymbolAddress((void**)&act, g_act);

    cudaFuncSetAttribute(gemm_tc<0>, cudaFuncAttributeMaxDynamicSharedMemorySize, SM_TOTAL);
    cudaFuncSetAttribute(gemm_tc<1>, cudaFuncAttributeMaxDynamicSharedMemorySize, SM_TOTAL);
    cudaFuncSetAttribute(gemm_tc<2>, cudaFuncAttributeMaxDynamicSharedMemorySize, SM_TOTAL);
    cudaFuncSetAttribute(gemm_tc<3>, cudaFuncAttributeMaxDynamicSharedMemorySize, SM_TOTAL);

    // 1. LN1 + shifted-window gather
    ln_kernel<<<NTOK / 8, 256>>>(x, n1g, n1b, xw, 1);
    // 2. QKV: M=100352, N=576, K=192
    gemm_tc<0><<<dim3(NTOK / GM, 576 / GN), 256, SM_TOTAL>>>(xw, qkv_w, qkv_b, qkv, nullptr, 192, 576);
    // 3. windowed attention (writes into xw)
    attn_k<<<dim3(NTOK / NWIN, NHEAD), 256>>>(qkv, rpb, xw);
    // 4. proj + scatter + residual -> d_out
    gemm_tc<1><<<dim3(NTOK / GM, CC / GN), 256, SM_TOTAL>>>(xw, proj_w, proj_b, out, x, 192, CC);
    // 5. LN2 (reuse qkv buffer)
    ln_kernel<<<NTOK / 8, 256>>>(out, n2g, n2b, qkv, 0);
    // 6. fc1 + GELU: N=768
    gemm_tc<2><<<dim3(NTOK / GM, HID / GN), 256, SM_TOTAL>>>(qkv, fc1w, fc1b, act, nullptr, 192, HID);
    // 7. fc2 + residual (in-place on d_out): K=768
    gemm_tc<3><<<dim3(NTOK / GM, CC / GN), 256, SM_TOTAL>>>(act, fc2w, fc2b, out, out, 768, CC);
}